// round 3
// baseline (speedup 1.0000x reference)
#include <cuda_runtime.h>
#include <math.h>

// ---------------- problem constants ----------------
#define Bn    16
#define Nn    15
#define Tn    50
#define NA    121
#define NR    40
#define Gd    4840            // NA*NR
#define G2    9680            // 2*Gd
#define K30   30              // 2*Nn
#define CP    1024            // padded column count (real columns = 800)
#define NITER 50
#define GS    80              // split-K blocks over g
#define GCH   121             // G2 / GS
#define CBLK  2               // column blocks (2 * 256 threads * 2 cols = 1024)

// ---------------- scratch (static device memory; no allocs) ----------------
__device__ float dA[K30 * G2];            // 1.16 MB  row-major [k][g]
__device__ float dX[G2 * CP];             // 39.6 MB  [g][c]
__device__ float dC[G2 * CP];             // 39.6 MB  [g][c]  = step*Aty
__device__ float dZ[K30 * CP];            // [k][c], pre-scaled by coef0
__device__ float dZpart[GS * K30 * CP];   // 9.8 MB split-K partials
__device__ float dYst[K30 * CP];          // stacked y [k][c]
__device__ float dM30[K30 * K30];         // Gram A A^T
__device__ float dParams[4];              // [0]=coef0=1/lambda, [1]=thr=0.3/lambda
__device__ float dNpart[10 * CP];         // norm partials
__device__ int   dMinIdx[Bn];

// ---------------- prep kernels ----------------
__global__ void k_build_yst(const float* __restrict__ yr, const float* __restrict__ yi) {
    int idx = blockIdx.x * 256 + threadIdx.x;       // over K30*CP = 30720
    if (idx >= K30 * CP) return;
    int k = idx / CP, c = idx % CP;
    float v = 0.0f;
    if (c < Bn * Tn) {
        int b = c / Tn, t = c % Tn;
        if (k < Nn) v = yr[(b * Nn + k) * Tn + t];
        else        v = yi[(b * Nn + (k - Nn)) * Tn + t];
    }
    dYst[idx] = v;
}

__global__ void k_build_A(const float* __restrict__ Ar, const float* __restrict__ Ai) {
    int idx = blockIdx.x * 256 + threadIdx.x;       // over K30*G2
    if (idx >= K30 * G2) return;
    int k = idx / G2, g = idx % G2;
    float v;
    if (k < Nn) {
        v = (g < Gd) ? Ar[k * Gd + g] : -Ai[k * Gd + (g - Gd)];
    } else {
        int kk = k - Nn;
        v = (g < Gd) ? Ai[kk * Gd + g] : Ar[kk * Gd + (g - Gd)];
    }
    dA[idx] = v;
}

// Gram M = A A^T  (30x30), one block per (i,j)
__global__ void k_gram() {
    int p = blockIdx.x;                 // 0..899
    int i = p / K30, j = p % K30;
    float s = 0.0f;
    for (int g = threadIdx.x; g < G2; g += 256)
        s += dA[i * G2 + g] * dA[j * G2 + g];
    __shared__ float red[256];
    red[threadIdx.x] = s;
    __syncthreads();
    for (int o = 128; o > 0; o >>= 1) {
        if (threadIdx.x < o) red[threadIdx.x] += red[threadIdx.x + o];
        __syncthreads();
    }
    if (threadIdx.x == 0) dM30[p] = red[0];
}

// lambda_max via 12 matrix squarings (effective power 4096) + Rayleigh quotient
__global__ void k_eig() {
    __shared__ float Ms[900];
    __shared__ float Mn[900];
    __shared__ float red[1024];
    int t = threadIdx.x;
    if (t < 900) Ms[t] = dM30[t];
    __syncthreads();
    for (int it = 0; it < 12; it++) {
        float v = 0.0f;
        if (t < 900) {
            int i = t / K30, j = t % K30;
            #pragma unroll 6
            for (int k = 0; k < K30; k++) v += Ms[i * K30 + k] * Ms[k * K30 + j];
            Mn[t] = v;
        }
        red[t] = (t < 900) ? v * v : 0.0f;
        __syncthreads();
        for (int o = 512; o > 0; o >>= 1) {
            if (t < o) red[t] += red[t + o];
            __syncthreads();
        }
        float inv = rsqrtf(red[0]);
        if (t < 900) Ms[t] = Mn[t] * inv;
        __syncthreads();
    }
    if (t == 0) {
        float v[K30]; float nv = 0.0f;
        for (int i = 0; i < K30; i++) {
            float s = 0.0f;
            for (int j = 0; j < K30; j++) s += Ms[i * K30 + j];
            v[i] = s; nv += s * s;
        }
        float inv = rsqrtf(nv);
        for (int i = 0; i < K30; i++) v[i] *= inv;
        float lam = 0.0f;
        for (int i = 0; i < K30; i++) {
            float w = 0.0f;
            for (int j = 0; j < K30; j++) w += dM30[i * K30 + j] * v[j];
            lam += v[i] * w;
        }
        // step = 30/lam; coef0 = step/30 = 1/lam; thr = 0.01*step = 0.3/lam
        dParams[0] = 1.0f / lam;
        dParams[1] = 0.3f / lam;
    }
}

// C = coef0 * A^T yst  : grid (CBLK, GS), block 256, 2 cols/thread
__global__ void __launch_bounds__(256) k_buildC() {
    __shared__ float As[K30 * GCH];
    int tid = threadIdx.x, cb = blockIdx.x, gs = blockIdx.y;
    int g0 = gs * GCH;
    for (int i = tid; i < K30 * GCH; i += 256) {
        int k = i / GCH, gl = i % GCH;
        As[i] = dA[k * G2 + g0 + gl];
    }
    __syncthreads();
    int c0 = (cb * 256 + tid) * 2;
    float y0[K30], y1[K30];
    #pragma unroll
    for (int k = 0; k < K30; k++) {
        float2 yv = *reinterpret_cast<const float2*>(&dYst[k * CP + c0]);
        y0[k] = yv.x; y1[k] = yv.y;
    }
    float coef0 = dParams[0];
    for (int gl = 0; gl < GCH; gl++) {
        float d0 = 0.0f, d1 = 0.0f;
        #pragma unroll
        for (int k = 0; k < K30; k++) {
            float a = As[k * GCH + gl];
            d0 += a * y0[k]; d1 += a * y1[k];
        }
        float2 ov; ov.x = coef0 * d0; ov.y = coef0 * d1;
        *reinterpret_cast<float2*>(&dC[(g0 + gl) * CP + c0]) = ov;
    }
}

// ---------------- iteration kernels ----------------
// K1: split-K partial Z = A * X ; grid (CBLK, GS)
__global__ void __launch_bounds__(256) k_ax() {
    __shared__ float As[K30 * GCH];
    int tid = threadIdx.x, cb = blockIdx.x, gs = blockIdx.y;
    int g0 = gs * GCH;
    for (int i = tid; i < K30 * GCH; i += 256) {
        int k = i / GCH, gl = i % GCH;
        As[i] = dA[k * G2 + g0 + gl];
    }
    __syncthreads();
    int c0 = (cb * 256 + tid) * 2;
    float a0[K30], a1[K30];
    #pragma unroll
    for (int k = 0; k < K30; k++) { a0[k] = 0.0f; a1[k] = 0.0f; }
    for (int gl = 0; gl < GCH; gl++) {
        float2 xv = *reinterpret_cast<const float2*>(&dX[(g0 + gl) * CP + c0]);
        #pragma unroll
        for (int k = 0; k < K30; k++) {
            float a = As[k * GCH + gl];
            a0[k] += a * xv.x; a1[k] += a * xv.y;
        }
    }
    float* zp = &dZpart[gs * (K30 * CP)];
    #pragma unroll
    for (int k = 0; k < K30; k++) {
        float2 v; v.x = a0[k]; v.y = a1[k];
        *reinterpret_cast<float2*>(&zp[k * CP + c0]) = v;
    }
}

// reduce split-K partials, fold coef0:  dZ = coef0 * sum_gs Zpart
__global__ void k_zred() {
    int e = blockIdx.x * 256 + threadIdx.x;     // < K30*CP = 30720
    float s = 0.0f;
    #pragma unroll 8
    for (int gs = 0; gs < GS; gs++) s += dZpart[gs * (K30 * CP) + e];
    dZ[e] = s * dParams[0];
}

// K2: X = soft(X + C - A^T * dZ, thr) ; grid (CBLK, GS)
__global__ void __launch_bounds__(256) k_update() {
    __shared__ float As[K30 * GCH];
    int tid = threadIdx.x, cb = blockIdx.x, gs = blockIdx.y;
    int g0 = gs * GCH;
    for (int i = tid; i < K30 * GCH; i += 256) {
        int k = i / GCH, gl = i % GCH;
        As[i] = dA[k * G2 + g0 + gl];
    }
    __syncthreads();
    int c0 = (cb * 256 + tid) * 2;
    float z0[K30], z1[K30];
    #pragma unroll
    for (int k = 0; k < K30; k++) {
        float2 zv = *reinterpret_cast<const float2*>(&dZ[k * CP + c0]);
        z0[k] = zv.x; z1[k] = zv.y;
    }
    float thr = dParams[1];
    for (int gl = 0; gl < GCH; gl++) {
        int row = (g0 + gl) * CP + c0;
        float d0 = 0.0f, d1 = 0.0f;
        #pragma unroll
        for (int k = 0; k < K30; k++) {
            float a = As[k * GCH + gl];
            d0 += a * z0[k]; d1 += a * z1[k];
        }
        float2 xv = *reinterpret_cast<const float2*>(&dX[row]);
        float2 cv = *reinterpret_cast<const float2*>(&dC[row]);
        float t0 = xv.x + cv.x - d0;
        float t1 = xv.y + cv.y - d1;
        float r0 = fmaxf(fabsf(t0) - thr, 0.0f);
        float r1 = fmaxf(fabsf(t1) - thr, 0.0f);
        float2 ov; ov.x = copysignf(r0, t0); ov.y = copysignf(r1, t1);
        *reinterpret_cast<float2*>(&dX[row]) = ov;
    }
}

// ---------------- epilogue ----------------
__global__ void k_norms() {          // grid (4, 10), block 256
    int c = blockIdx.x * 256 + threadIdx.x;   // < CP
    int j = blockIdx.y;
    int gstart = j * (Gd / 10);               // 484
    float s = 0.0f;
    for (int gl = 0; gl < Gd / 10; gl++) {
        int g = gstart + gl;
        float xr = dX[g * CP + c];
        float xi = dX[(g + Gd) * CP + c];
        s += sqrtf(xr * xr + xi * xi + 1e-12f);
    }
    dNpart[j * CP + c] = s;
}

__global__ void k_argmin() {         // <<<1,32>>>
    int b = threadIdx.x;
    if (b >= Bn) return;
    float best = 3.4e38f; int bi = 0;
    for (int t = 0; t < Tn; t++) {
        float v = 0.0f;
        for (int j = 0; j < 10; j++) v += dNpart[j * CP + b * Tn + t];
        if (v < best) { best = v; bi = t; }
    }
    dMinIdx[b] = bi;
}

__global__ void k_s(float* __restrict__ out) {   // grid (19, Bn), block 256
    __shared__ int cc[Bn];
    if (threadIdx.x < Bn) cc[threadIdx.x] = blockIdx.y * Tn + dMinIdx[threadIdx.x];
    __syncthreads();
    int g = blockIdx.x * 256 + threadIdx.x;
    int b = blockIdx.y;
    if (g >= Gd) return;
    float acc = 0.0f;
    #pragma unroll
    for (int bp = 0; bp < Bn; bp++) {
        int c = cc[bp];
        float xr = dX[g * CP + c];
        float xi = dX[(g + Gd) * CP + c];
        acc += sqrtf(xr * xr + xi * xi + 1e-12f);
    }
    out[64 + b * Gd + g] = acc * (1.0f / Bn);
}

__global__ void k_topk(const float* __restrict__ angles,
                       const float* __restrict__ ranges,
                       float* __restrict__ out) {  // <<<Bn,256>>>
    int b = blockIdx.x;
    const float* s = out + 64 + b * Gd;
    __shared__ float sv[256];
    __shared__ int   si[256];
    // pass 1: global max (tie -> smaller index)
    float bv = -3.4e38f; int bi = 0;
    for (int g = threadIdx.x; g < Gd; g += 256) {
        float v = s[g];
        if (v > bv || (v == bv && g < bi)) { bv = v; bi = g; }
    }
    sv[threadIdx.x] = bv; si[threadIdx.x] = bi;
    __syncthreads();
    for (int o = 128; o > 0; o >>= 1) {
        if (threadIdx.x < o) {
            float v2 = sv[threadIdx.x + o]; int i2 = si[threadIdx.x + o];
            if (v2 > sv[threadIdx.x] || (v2 == sv[threadIdx.x] && i2 < si[threadIdx.x])) {
                sv[threadIdx.x] = v2; si[threadIdx.x] = i2;
            }
        }
        __syncthreads();
    }
    float v1 = sv[0]; int i1 = si[0];
    __syncthreads();
    // pass 2: max excluding i1
    bv = -3.4e38f; bi = 0;
    for (int g = threadIdx.x; g < Gd; g += 256) {
        if (g == i1) continue;
        float v = s[g];
        if (v > bv || (v == bv && g < bi)) { bv = v; bi = g; }
    }
    sv[threadIdx.x] = bv; si[threadIdx.x] = bi;
    __syncthreads();
    for (int o = 128; o > 0; o >>= 1) {
        if (threadIdx.x < o) {
            float v2 = sv[threadIdx.x + o]; int i2 = si[threadIdx.x + o];
            if (v2 > sv[threadIdx.x] || (v2 == sv[threadIdx.x] && i2 < si[threadIdx.x])) {
                sv[threadIdx.x] = v2; si[threadIdx.x] = i2;
            }
        }
        __syncthreads();
    }
    if (threadIdx.x == 0) {
        int i2 = si[0];
        (void)v1;
        out[b * 2 + 0]      = angles[i1 / NR];
        out[b * 2 + 1]      = angles[i2 / NR];
        out[32 + b * 2 + 0] = ranges[i1 % NR];
        out[32 + b * 2 + 1] = ranges[i2 % NR];
    }
}

// ---------------- launch ----------------
extern "C" void kernel_launch(void* const* d_in, const int* in_sizes, int n_in,
                              void* d_out, int out_size) {
    const float* y_real = (const float*)d_in[0];
    const float* y_imag = (const float*)d_in[1];
    const float* A_real = (const float*)d_in[2];
    const float* A_imag = (const float*)d_in[3];
    const float* angles = (const float*)d_in[4];
    const float* ranges = (const float*)d_in[5];
    float* out = (float*)d_out;

    void* pX = nullptr;
    cudaGetSymbolAddress(&pX, dX);
    cudaMemsetAsync(pX, 0, sizeof(float) * (size_t)G2 * CP);

    k_build_yst<<<(K30 * CP + 255) / 256, 256>>>(y_real, y_imag);
    k_build_A<<<(K30 * G2 + 255) / 256, 256>>>(A_real, A_imag);
    k_gram<<<K30 * K30, 256>>>();
    k_eig<<<1, 1024>>>();

    dim3 gmain(CBLK, GS);
    k_buildC<<<gmain, 256>>>();

    for (int it = 0; it < NITER; it++) {
        k_ax<<<gmain, 256>>>();
        k_zred<<<(K30 * CP + 255) / 256, 256>>>();
        k_update<<<gmain, 256>>>();
    }

    k_norms<<<dim3(4, 10), 256>>>();
    k_argmin<<<1, 32>>>();
    k_s<<<dim3((Gd + 255) / 256, Bn), 256>>>(out);
    k_topk<<<Bn, 256>>>(angles, ranges, out);
}